// round 2
// baseline (speedup 1.0000x reference)
#include <cuda_runtime.h>
#include <math.h>
#include <stdint.h>

// Problem constants
#define B_ 2
#define Q_ 75
#define N_ 5
#define T_ 196
#define C_ 384
#define D_ 384

#define TPB 256
#define DT 64            // d-slab (rows of S per slab)
#define NSLAB (C_ / DT)  // 6
#define KP1 13           // GEMM1 k16 panels (K padded 196 -> 208)
#define KP2 24           // GEMM2 k16 panels (K = 384)
#define NT2 224          // GEMM2 N (t padded 196 -> 224)
#define PEX_LD 388       // padded row stride for Pexp slab

// Shared memory layout (in floats)
#define OFF_PEX  0                          // Pexp slab [64][388]
#define OFF_B    (OFF_PEX + DT * PEX_LD)    // packed B panels: [2 planes][2 kk][48 G][32] float2
#define OFF_A    (OFF_B + 2 * 2 * 48 * 64)  // packed A panels: [2 planes][2 kk][4 T][32] float4
#define OFF_RINV (OFF_A + 2 * 2 * 4 * 128)  // 1/rowsum [64]
#define OFF_PN   (OFF_RINV + 64)            // per-warp num partials [8][224]
#define OFF_PQ   (OFF_PN + 8 * NT2)         // per-warp norm2 partials [8][224]
#define OFF_NFS  (OFF_PQ + 8 * NT2)         // Fs token norms [224]
#define OFF_RED  (OFF_NFS + NT2)            // [8]
#define SMEM_FLOATS (OFF_RED + 8)

__device__ float g_top1[B_ * Q_ * N_];

__device__ __forceinline__ uint32_t tf32_rna(float x) {
    uint32_t u;
    asm("cvt.rna.tf32.f32 %0, %1;" : "=r"(u) : "f"(x));
    return u;
}

__device__ __forceinline__ void split_tf32(float x, float& hi, float& lo) {
    uint32_t h = tf32_rna(x);
    hi = __uint_as_float(h);
    lo = __uint_as_float(tf32_rna(x - hi));
}

__device__ __forceinline__ void mma8(float* c, uint32_t a0, uint32_t a1,
                                     uint32_t a2, uint32_t a3,
                                     uint32_t b0, uint32_t b1) {
    asm volatile(
        "mma.sync.aligned.m16n8k8.row.col.f32.tf32.tf32.f32 "
        "{%0,%1,%2,%3}, {%4,%5,%6,%7}, {%8,%9}, {%0,%1,%2,%3};"
        : "+f"(c[0]), "+f"(c[1]), "+f"(c[2]), "+f"(c[3])
        : "r"(a0), "r"(a1), "r"(a2), "r"(a3), "r"(b0), "r"(b1));
}

__global__ __launch_bounds__(TPB, 1)
void episodic_tc_kernel(const float* __restrict__ fq_g,
                        const float* __restrict__ fs_g) {
    extern __shared__ float sm[];
    float*  sPex  = sm + OFF_PEX;
    float2* sB    = (float2*)(sm + OFF_B);   // idx: ((plane*2+kk)*48+G)*32 + lane
    float4* sA    = (float4*)(sm + OFF_A);   // idx: ((plane*2+kk)*4+T)*32 + lane
    float*  sRinv = sm + OFF_RINV;
    float*  sPN   = sm + OFF_PN;
    float*  sPQ   = sm + OFF_PQ;
    float*  sNfs  = sm + OFF_NFS;
    float*  sRed  = sm + OFF_RED;

    const int bx = blockIdx.x;
    const int nn = bx % N_;
    const int qq = (bx / N_) % Q_;
    const int bb = bx / (N_ * Q_);
    const float* __restrict__ Fq = fq_g + (size_t)(bb * Q_ + qq) * T_ * C_;
    const float* __restrict__ Fs = fs_g + (size_t)(bb * N_ + nn) * T_ * C_;

    const int tid  = threadIdx.x;
    const int wid  = tid >> 5;
    const int lane = tid & 31;
    const int wm   = wid >> 2;   // warp m-row (0..1)
    const int wn   = wid & 3;    // warp n-col (0..3)
    const int gr   = lane >> 2;  // mma groupID (row)
    const int gc   = lane & 3;   // mma threadID-in-group (col)
    const float scale = 1.0f / 14.0f;

    // ---- init partials + Fs token norms ----
    for (int i = tid; i < 8 * NT2; i += TPB) { sPN[i] = 0.f; sPQ[i] = 0.f; }
    for (int r = wid; r < T_; r += 8) {
        float s = 0.f;
        #pragma unroll
        for (int u = 0; u < C_ / 32; u++) {
            float v = Fs[r * C_ + lane + 32 * u];
            s += v * v;
        }
        #pragma unroll
        for (int o = 16; o > 0; o >>= 1) s += __shfl_xor_sync(0xffffffffu, s, o);
        if (lane == 0) sNfs[r] = sqrtf(s);
    }
    __syncthreads();

    // ===================== d-slab loop =====================
    for (int slab = 0; slab < NSLAB; slab++) {
        const int d0 = slab * DT;

        // -------- GEMM1: S[64][384] = scale * Fq(:,d0:d0+64)^T @ Fs --------
        float acc1[2][12][4];
        #pragma unroll
        for (int mt = 0; mt < 2; mt++)
            #pragma unroll
            for (int nt = 0; nt < 12; nt++)
                #pragma unroll
                for (int e = 0; e < 4; e++) acc1[mt][nt][e] = 0.f;

        for (int p = 0; p < KP1; p++) {
            const int t0 = p * 16;
            // stage B1 panel: B[k][n] = Fs[t0+k][n], packed frag pairs, hi/lo
            for (int u = tid; u < 2 * 4 * 48; u += TPB) {
                int kk = u / 192;
                int rm = u % 192;
                int c  = rm / 48;
                int G  = rm % 48;
                int ta = t0 + kk * 8 + c;
                int tb = ta + 4;
                float ra[8], rb[8];
                if (ta < T_) {
                    float4 v0 = *(const float4*)&Fs[ta * C_ + 8 * G];
                    float4 v1 = *(const float4*)&Fs[ta * C_ + 8 * G + 4];
                    ra[0]=v0.x; ra[1]=v0.y; ra[2]=v0.z; ra[3]=v0.w;
                    ra[4]=v1.x; ra[5]=v1.y; ra[6]=v1.z; ra[7]=v1.w;
                } else {
                    #pragma unroll
                    for (int g = 0; g < 8; g++) ra[g] = 0.f;
                }
                if (tb < T_) {
                    float4 v0 = *(const float4*)&Fs[tb * C_ + 8 * G];
                    float4 v1 = *(const float4*)&Fs[tb * C_ + 8 * G + 4];
                    rb[0]=v0.x; rb[1]=v0.y; rb[2]=v0.z; rb[3]=v0.w;
                    rb[4]=v1.x; rb[5]=v1.y; rb[6]=v1.z; rb[7]=v1.w;
                } else {
                    #pragma unroll
                    for (int g = 0; g < 8; g++) rb[g] = 0.f;
                }
                #pragma unroll
                for (int g = 0; g < 8; g++) {
                    float ha, la, hb, lb;
                    split_tf32(ra[g], ha, la);
                    split_tf32(rb[g], hb, lb);
                    sB[((0 * 2 + kk) * 48 + G) * 32 + g * 4 + c] = make_float2(ha, hb);
                    sB[((1 * 2 + kk) * 48 + G) * 32 + g * 4 + c] = make_float2(la, lb);
                }
            }
            // stage A1 panel (one unit per thread): A[m][k] = scale*Fq[t0+k][d0+m]
            {
                int kk = tid >> 7;
                int T  = (tid >> 5) & 3;
                int l  = tid & 31;
                int r  = l >> 2;
                int c  = l & 3;
                int ta = t0 + kk * 8 + c;
                int tb = ta + 4;
                int d1 = d0 + T * 16 + r;
                int d2 = d1 + 8;
                float x0 = (ta < T_) ? Fq[ta * C_ + d1] * scale : 0.f;
                float x1 = (ta < T_) ? Fq[ta * C_ + d2] * scale : 0.f;
                float x2 = (tb < T_) ? Fq[tb * C_ + d1] * scale : 0.f;
                float x3 = (tb < T_) ? Fq[tb * C_ + d2] * scale : 0.f;
                float h0,l0,h1,l1,h2,l2,h3,l3;
                split_tf32(x0, h0, l0); split_tf32(x1, h1, l1);
                split_tf32(x2, h2, l2); split_tf32(x3, h3, l3);
                sA[((0 * 2 + kk) * 4 + T) * 32 + l] = make_float4(h0, h1, h2, h3);
                sA[((1 * 2 + kk) * 4 + T) * 32 + l] = make_float4(l0, l1, l2, l3);
            }
            __syncthreads();
            #pragma unroll
            for (int kk = 0; kk < 2; kk++) {
                uint32_t ah[2][4], al[2][4];
                #pragma unroll
                for (int mt = 0; mt < 2; mt++) {
                    int T = wm * 2 + mt;
                    float4 h = sA[((0 * 2 + kk) * 4 + T) * 32 + lane];
                    float4 l = sA[((1 * 2 + kk) * 4 + T) * 32 + lane];
                    ah[mt][0]=__float_as_uint(h.x); ah[mt][1]=__float_as_uint(h.y);
                    ah[mt][2]=__float_as_uint(h.z); ah[mt][3]=__float_as_uint(h.w);
                    al[mt][0]=__float_as_uint(l.x); al[mt][1]=__float_as_uint(l.y);
                    al[mt][2]=__float_as_uint(l.z); al[mt][3]=__float_as_uint(l.w);
                }
                #pragma unroll
                for (int nt = 0; nt < 12; nt++) {
                    int G = wn * 12 + nt;
                    float2 bh = sB[((0 * 2 + kk) * 48 + G) * 32 + lane];
                    float2 bl = sB[((1 * 2 + kk) * 48 + G) * 32 + lane];
                    uint32_t bh0 = __float_as_uint(bh.x), bh1 = __float_as_uint(bh.y);
                    uint32_t bl0 = __float_as_uint(bl.x), bl1 = __float_as_uint(bl.y);
                    #pragma unroll
                    for (int mt = 0; mt < 2; mt++) {
                        mma8(acc1[mt][nt], ah[mt][0], ah[mt][1], ah[mt][2], ah[mt][3], bh0, bh1);
                        mma8(acc1[mt][nt], ah[mt][0], ah[mt][1], ah[mt][2], ah[mt][3], bl0, bl1);
                        mma8(acc1[mt][nt], al[mt][0], al[mt][1], al[mt][2], al[mt][3], bh0, bh1);
                    }
                }
            }
            __syncthreads();
        }

        // write S slab to sPex
        #pragma unroll
        for (int mt = 0; mt < 2; mt++) {
            int row = wm * 32 + mt * 16 + gr;
            #pragma unroll
            for (int nt = 0; nt < 12; nt++) {
                int col = wn * 96 + nt * 8 + 2 * gc;
                sPex[row * PEX_LD + col]           = acc1[mt][nt][0];
                sPex[row * PEX_LD + col + 1]       = acc1[mt][nt][1];
                sPex[(row + 8) * PEX_LD + col]     = acc1[mt][nt][2];
                sPex[(row + 8) * PEX_LD + col + 1] = acc1[mt][nt][3];
            }
        }
        __syncthreads();

        // -------- row softmax (unnormalized exp; rowsum deferred) --------
        #pragma unroll
        for (int rr = 0; rr < DT / 8; rr++) {
            int row = wid * (DT / 8) + rr;
            float v[C_ / 32];
            float mx = -INFINITY;
            #pragma unroll
            for (int u = 0; u < C_ / 32; u++) {
                v[u] = sPex[row * PEX_LD + lane + 32 * u];
                mx = fmaxf(mx, v[u]);
            }
            #pragma unroll
            for (int o = 16; o > 0; o >>= 1)
                mx = fmaxf(mx, __shfl_xor_sync(0xffffffffu, mx, o));
            float ssum = 0.f;
            #pragma unroll
            for (int u = 0; u < C_ / 32; u++) {
                v[u] = __expf(v[u] - mx);
                ssum += v[u];
            }
            #pragma unroll
            for (int o = 16; o > 0; o >>= 1)
                ssum += __shfl_xor_sync(0xffffffffu, ssum, o);
            #pragma unroll
            for (int u = 0; u < C_ / 32; u++)
                sPex[row * PEX_LD + lane + 32 * u] = v[u];
            if (lane == 0) sRinv[row] = 1.0f / ssum;
        }
        __syncthreads();

        // -------- GEMM2: fq_new^T[64][224] = Pexp[64][384] @ Fq^T --------
        float acc2[2][7][4];
        #pragma unroll
        for (int mt = 0; mt < 2; mt++)
            #pragma unroll
            for (int nt = 0; nt < 7; nt++)
                #pragma unroll
                for (int e = 0; e < 4; e++) acc2[mt][nt][e] = 0.f;

        for (int p = 0; p < KP2; p++) {
            const int c0 = p * 16;
            // stage B2: B[k][n] = Fq[t=n][c0+k]
            if (tid < 2 * 4 * 28) {
                int u  = tid;
                int kk = u / 112;
                int rm = u % 112;
                int c  = rm / 28;
                int G  = rm % 28;
                int ck = c0 + kk * 8 + c;
                #pragma unroll
                for (int g = 0; g < 8; g++) {
                    int t = 8 * G + g;
                    float va = (t < T_) ? Fq[t * C_ + ck]     : 0.f;
                    float vb = (t < T_) ? Fq[t * C_ + ck + 4] : 0.f;
                    float ha, la, hb, lb;
                    split_tf32(va, ha, la);
                    split_tf32(vb, hb, lb);
                    sB[((0 * 2 + kk) * 48 + G) * 32 + g * 4 + c] = make_float2(ha, hb);
                    sB[((1 * 2 + kk) * 48 + G) * 32 + g * 4 + c] = make_float2(la, lb);
                }
            }
            // stage A2 (one per thread): A[m][k] = Pexp[m][c0+k]
            {
                int kk = tid >> 7;
                int T  = (tid >> 5) & 3;
                int l  = tid & 31;
                int r  = l >> 2;
                int c  = l & 3;
                int ck = c0 + kk * 8 + c;
                float x0 = sPex[(T * 16 + r) * PEX_LD + ck];
                float x1 = sPex[(T * 16 + r + 8) * PEX_LD + ck];
                float x2 = sPex[(T * 16 + r) * PEX_LD + ck + 4];
                float x3 = sPex[(T * 16 + r + 8) * PEX_LD + ck + 4];
                float h0,l0,h1,l1,h2,l2,h3,l3;
                split_tf32(x0, h0, l0); split_tf32(x1, h1, l1);
                split_tf32(x2, h2, l2); split_tf32(x3, h3, l3);
                sA[((0 * 2 + kk) * 4 + T) * 32 + l] = make_float4(h0, h1, h2, h3);
                sA[((1 * 2 + kk) * 4 + T) * 32 + l] = make_float4(l0, l1, l2, l3);
            }
            __syncthreads();
            #pragma unroll
            for (int kk = 0; kk < 2; kk++) {
                uint32_t ah[2][4], al[2][4];
                #pragma unroll
                for (int mt = 0; mt < 2; mt++) {
                    int T = wm * 2 + mt;
                    float4 h = sA[((0 * 2 + kk) * 4 + T) * 32 + lane];
                    float4 l = sA[((1 * 2 + kk) * 4 + T) * 32 + lane];
                    ah[mt][0]=__float_as_uint(h.x); ah[mt][1]=__float_as_uint(h.y);
                    ah[mt][2]=__float_as_uint(h.z); ah[mt][3]=__float_as_uint(h.w);
                    al[mt][0]=__float_as_uint(l.x); al[mt][1]=__float_as_uint(l.y);
                    al[mt][2]=__float_as_uint(l.z); al[mt][3]=__float_as_uint(l.w);
                }
                #pragma unroll
                for (int nt = 0; nt < 7; nt++) {
                    int G = wn * 7 + nt;
                    float2 bh = sB[((0 * 2 + kk) * 48 + G) * 32 + lane];
                    float2 bl = sB[((1 * 2 + kk) * 48 + G) * 32 + lane];
                    uint32_t bh0 = __float_as_uint(bh.x), bh1 = __float_as_uint(bh.y);
                    uint32_t bl0 = __float_as_uint(bl.x), bl1 = __float_as_uint(bl.y);
                    #pragma unroll
                    for (int mt = 0; mt < 2; mt++) {
                        mma8(acc2[mt][nt], ah[mt][0], ah[mt][1], ah[mt][2], ah[mt][3], bh0, bh1);
                        mma8(acc2[mt][nt], ah[mt][0], ah[mt][1], ah[mt][2], ah[mt][3], bl0, bl1);
                        mma8(acc2[mt][nt], al[mt][0], al[mt][1], al[mt][2], al[mt][3], bh0, bh1);
                    }
                }
            }
            __syncthreads();
        }

        // -------- epilogue: fold 1/rowsum, num/norm2 partials --------
        #pragma unroll
        for (int mt = 0; mt < 2; mt++) {
            int dl1 = wm * 32 + mt * 16 + gr;
            int dl2 = dl1 + 8;
            float rd1 = sRinv[dl1];
            float rd2 = sRinv[dl2];
            int gd1 = d0 + dl1;
            int gd2 = d0 + dl2;
            #pragma unroll
            for (int nt = 0; nt < 7; nt++) {
                int ta = wn * 56 + nt * 8 + 2 * gc;
                int tb = ta + 1;
                float v0 = acc2[mt][nt][0] * rd1;
                float v1 = acc2[mt][nt][1] * rd1;
                float v2 = acc2[mt][nt][2] * rd2;
                float v3 = acc2[mt][nt][3] * rd2;
                float fa1 = 0.f, fa2 = 0.f, fb1 = 0.f, fb2 = 0.f;
                if (ta < T_) { fa1 = Fs[ta * C_ + gd1]; fa2 = Fs[ta * C_ + gd2]; }
                if (tb < T_) { fb1 = Fs[tb * C_ + gd1]; fb2 = Fs[tb * C_ + gd2]; }
                float pn_a = v0 * fa1 + v2 * fa2;
                float pq_a = v0 * v0 + v2 * v2;
                float pn_b = v1 * fb1 + v3 * fb2;
                float pq_b = v1 * v1 + v3 * v3;
                #pragma unroll
                for (int o = 4; o <= 16; o <<= 1) {
                    pn_a += __shfl_xor_sync(0xffffffffu, pn_a, o);
                    pq_a += __shfl_xor_sync(0xffffffffu, pq_a, o);
                    pn_b += __shfl_xor_sync(0xffffffffu, pn_b, o);
                    pq_b += __shfl_xor_sync(0xffffffffu, pq_b, o);
                }
                if (lane < 4) {
                    sPN[wid * NT2 + ta] += pn_a;
                    sPQ[wid * NT2 + ta] += pq_a;
                    sPN[wid * NT2 + tb] += pn_b;
                    sPQ[wid * NT2 + tb] += pq_b;
                }
            }
        }
        __syncthreads();
    }  // slab loop

    // ---- cosine sim per token, max over tokens ----
    float local = -INFINITY;
    for (int t = tid; t < T_; t += TPB) {
        float num = 0.f, nrm = 0.f;
        #pragma unroll
        for (int w = 0; w < 8; w++) {
            num += sPN[w * NT2 + t];
            nrm += sPQ[w * NT2 + t];
        }
        float denom = fmaxf(sqrtf(nrm) * sNfs[t], 1e-8f);
        local = fmaxf(local, num / denom);
    }
    #pragma unroll
    for (int o = 16; o > 0; o >>= 1)
        local = fmaxf(local, __shfl_xor_sync(0xffffffffu, local, o));
    if (lane == 0) sRed[wid] = local;
    __syncthreads();
    if (tid == 0) {
        float m = sRed[0];
        #pragma unroll
        for (int w = 1; w < 8; w++) m = fmaxf(m, sRed[w]);
        g_top1[bx] = m;
    }
}

__global__ void finalize_logits_kernel(float* __restrict__ out) {
    int i = blockIdx.x * blockDim.x + threadIdx.x;
    if (i < B_ * Q_) {
        float s = 0.f;
        #pragma unroll
        for (int n = 0; n < N_; n++) s += g_top1[i * N_ + n];
        out[i] = s * (1.0f / N_);
    }
}

__global__ void cls_kernel(const float* __restrict__ xq,
                           const float* __restrict__ xs,
                           float* __restrict__ out) {
    int w = (blockIdx.x * blockDim.x + threadIdx.x) >> 5;
    int lid = threadIdx.x & 31;
    if (w >= B_ * Q_ * N_) return;
    int nn = w % N_;
    int qq = (w / N_) % Q_;
    int bb = w / (N_ * Q_);
    const float* q = xq + (size_t)(bb * Q_ + qq) * D_;
    const float* s = xs + (size_t)(bb * N_ + nn) * D_;
    float dot = 0.f, nq = 0.f, ns = 0.f;
    #pragma unroll
    for (int u = 0; u < D_ / 32; u++) {
        float a = q[lid + 32 * u];
        float b = s[lid + 32 * u];
        dot += a * b;
        nq += a * a;
        ns += b * b;
    }
    #pragma unroll
    for (int o = 16; o > 0; o >>= 1) {
        dot += __shfl_xor_sync(0xffffffffu, dot, o);
        nq  += __shfl_xor_sync(0xffffffffu, nq, o);
        ns  += __shfl_xor_sync(0xffffffffu, ns, o);
    }
    if (lid == 0) {
        float den = fmaxf(sqrtf(nq), 1e-12f) * fmaxf(sqrtf(ns), 1e-12f);
        out[B_ * Q_ + w] = 10.0f * dot / den;
    }
}

extern "C" void kernel_launch(void* const* d_in, const int* in_sizes, int n_in,
                              void* d_out, int out_size) {
    const float* fq = (const float*)d_in[0];  // (2,75,196,384)
    const float* fs = (const float*)d_in[1];  // (2,5,1,196,384)
    const float* xq = (const float*)d_in[2];  // (2,75,384)
    const float* xs = (const float*)d_in[3];  // (2,5,1,384)
    float* out = (float*)d_out;               // [150 logits][750 cls_logits]

    const size_t smem_bytes = (size_t)SMEM_FLOATS * sizeof(float);
    cudaFuncSetAttribute(episodic_tc_kernel,
                         cudaFuncAttributeMaxDynamicSharedMemorySize,
                         (int)smem_bytes);

    episodic_tc_kernel<<<B_ * Q_ * N_, TPB, smem_bytes>>>(fq, fs);
    finalize_logits_kernel<<<1, 256>>>(out);
    cls_kernel<<<(B_ * Q_ * N_ * 32 + 255) / 256, 256>>>(xq, xs, out);
}

// round 3
// speedup vs baseline: 1.0003x; 1.0003x over previous
#include <cuda_runtime.h>
#include <math.h>
#include <stdint.h>

// Problem constants
#define B_ 2
#define Q_ 75
#define N_ 5
#define T_ 196
#define C_ 384
#define D_ 384

#define TPB 256
#define DT 64            // d-slab (rows of S per slab)
#define NSLAB (C_ / DT)  // 6
#define KP1 13           // GEMM1 k16 panels (K padded 196 -> 208)
#define KP2 24           // GEMM2 k16 panels (K = 384)
#define NT2 224          // GEMM2 N (t padded 196 -> 224)
#define PEX_LD 388       // padded row stride for Pexp slab

// Shared memory layout (in floats)
#define OFF_PEX  0                          // Pexp slab [64][388]
#define OFF_B    (OFF_PEX + DT * PEX_LD)    // packed B panels: [2 planes][2 kk][48 G][32] float2
#define OFF_A    (OFF_B + 2 * 2 * 48 * 64)  // packed A panels: [2 planes][2 kk][4 T][32] float4
#define OFF_RINV (OFF_A + 2 * 2 * 4 * 128)  // 1/rowsum [64]
#define OFF_PN   (OFF_RINV + 64)            // per-warp num partials [8][224]
#define OFF_PQ   (OFF_PN + 8 * NT2)         // per-warp norm2 partials [8][224]
#define OFF_NFS  (OFF_PQ + 8 * NT2)         // Fs token norms [224]
#define OFF_RED  (OFF_NFS + NT2)            // [8]
#define SMEM_FLOATS (OFF_RED + 8)

__device__ float g_top1[B_ * Q_ * N_];

__device__ __forceinline__ uint32_t tf32_rna(float x) {
    uint32_t u;
    asm("cvt.rna.tf32.f32 %0, %1;" : "=r"(u) : "f"(x));
    return u;
}

__device__ __forceinline__ void split_tf32(float x, float& hi, float& lo) {
    uint32_t h = tf32_rna(x);
    hi = __uint_as_float(h);
    lo = __uint_as_float(tf32_rna(x - hi));
}

__device__ __forceinline__ void mma8(float* c, uint32_t a0, uint32_t a1,
                                     uint32_t a2, uint32_t a3,
                                     uint32_t b0, uint32_t b1) {
    asm volatile(
        "mma.sync.aligned.m16n8k8.row.col.f32.tf32.tf32.f32 "
        "{%0,%1,%2,%3}, {%4,%5,%6,%7}, {%8,%9}, {%0,%1,%2,%3};"
        : "+f"(c[0]), "+f"(c[1]), "+f"(c[2]), "+f"(c[3])
        : "r"(a0), "r"(a1), "r"(a2), "r"(a3), "r"(b0), "r"(b1));
}

__global__ __launch_bounds__(TPB, 1)
void episodic_tc_kernel(const float* __restrict__ fq_g,
                        const float* __restrict__ fs_g) {
    extern __shared__ float sm[];
    float*  sPex  = sm + OFF_PEX;
    float2* sB    = (float2*)(sm + OFF_B);   // idx: ((plane*2+kk)*48+G)*32 + lane
    float4* sA    = (float4*)(sm + OFF_A);   // idx: ((plane*2+kk)*4+T)*32 + lane
    float*  sRinv = sm + OFF_RINV;
    float*  sPN   = sm + OFF_PN;
    float*  sPQ   = sm + OFF_PQ;
    float*  sNfs  = sm + OFF_NFS;
    float*  sRed  = sm + OFF_RED;

    const int bx = blockIdx.x;
    const int nn = bx % N_;
    const int qq = (bx / N_) % Q_;
    const int bb = bx / (N_ * Q_);
    const float* __restrict__ Fq = fq_g + (size_t)(bb * Q_ + qq) * T_ * C_;
    const float* __restrict__ Fs = fs_g + (size_t)(bb * N_ + nn) * T_ * C_;

    const int tid  = threadIdx.x;
    const int wid  = tid >> 5;
    const int lane = tid & 31;
    const int wm   = wid >> 2;   // warp m-row (0..1)
    const int wn   = wid & 3;    // warp n-col (0..3)
    const int gr   = lane >> 2;  // mma groupID (row)
    const int gc   = lane & 3;   // mma threadID-in-group (col)
    const float scale = 1.0f / 14.0f;

    // ---- init partials + Fs token norms ----
    for (int i = tid; i < 8 * NT2; i += TPB) { sPN[i] = 0.f; sPQ[i] = 0.f; }
    for (int r = wid; r < T_; r += 8) {
        float s = 0.f;
        #pragma unroll
        for (int u = 0; u < C_ / 32; u++) {
            float v = Fs[r * C_ + lane + 32 * u];
            s += v * v;
        }
        #pragma unroll
        for (int o = 16; o > 0; o >>= 1) s += __shfl_xor_sync(0xffffffffu, s, o);
        if (lane == 0) sNfs[r] = sqrtf(s);
    }
    __syncthreads();

    // ===================== d-slab loop =====================
    for (int slab = 0; slab < NSLAB; slab++) {
        const int d0 = slab * DT;

        // -------- GEMM1: S[64][384] = scale * Fq(:,d0:d0+64)^T @ Fs --------
        float acc1[2][12][4];
        #pragma unroll
        for (int mt = 0; mt < 2; mt++)
            #pragma unroll
            for (int nt = 0; nt < 12; nt++)
                #pragma unroll
                for (int e = 0; e < 4; e++) acc1[mt][nt][e] = 0.f;

        for (int p = 0; p < KP1; p++) {
            const int t0 = p * 16;
            // stage B1 panel: B[k][n] = Fs[t0+k][n], packed frag pairs, hi/lo
            for (int u = tid; u < 2 * 4 * 48; u += TPB) {
                int kk = u / 192;
                int rm = u % 192;
                int c  = rm / 48;
                int G  = rm % 48;
                int ta = t0 + kk * 8 + c;
                int tb = ta + 4;
                float ra[8], rb[8];
                if (ta < T_) {
                    float4 v0 = *(const float4*)&Fs[ta * C_ + 8 * G];
                    float4 v1 = *(const float4*)&Fs[ta * C_ + 8 * G + 4];
                    ra[0]=v0.x; ra[1]=v0.y; ra[2]=v0.z; ra[3]=v0.w;
                    ra[4]=v1.x; ra[5]=v1.y; ra[6]=v1.z; ra[7]=v1.w;
                } else {
                    #pragma unroll
                    for (int g = 0; g < 8; g++) ra[g] = 0.f;
                }
                if (tb < T_) {
                    float4 v0 = *(const float4*)&Fs[tb * C_ + 8 * G];
                    float4 v1 = *(const float4*)&Fs[tb * C_ + 8 * G + 4];
                    rb[0]=v0.x; rb[1]=v0.y; rb[2]=v0.z; rb[3]=v0.w;
                    rb[4]=v1.x; rb[5]=v1.y; rb[6]=v1.z; rb[7]=v1.w;
                } else {
                    #pragma unroll
                    for (int g = 0; g < 8; g++) rb[g] = 0.f;
                }
                #pragma unroll
                for (int g = 0; g < 8; g++) {
                    float ha, la, hb, lb;
                    split_tf32(ra[g], ha, la);
                    split_tf32(rb[g], hb, lb);
                    sB[((0 * 2 + kk) * 48 + G) * 32 + g * 4 + c] = make_float2(ha, hb);
                    sB[((1 * 2 + kk) * 48 + G) * 32 + g * 4 + c] = make_float2(la, lb);
                }
            }
            // stage A1 panel (one unit per thread): A[m][k] = scale*Fq[t0+k][d0+m]
            {
                int kk = tid >> 7;
                int T  = (tid >> 5) & 3;
                int l  = tid & 31;
                int r  = l >> 2;
                int c  = l & 3;
                int ta = t0 + kk * 8 + c;
                int tb = ta + 4;
                int d1 = d0 + T * 16 + r;
                int d2 = d1 + 8;
                float x0 = (ta < T_) ? Fq[ta * C_ + d1] * scale : 0.f;
                float x1 = (ta < T_) ? Fq[ta * C_ + d2] * scale : 0.f;
                float x2 = (tb < T_) ? Fq[tb * C_ + d1] * scale : 0.f;
                float x3 = (tb < T_) ? Fq[tb * C_ + d2] * scale : 0.f;
                float h0,l0,h1,l1,h2,l2,h3,l3;
                split_tf32(x0, h0, l0); split_tf32(x1, h1, l1);
                split_tf32(x2, h2, l2); split_tf32(x3, h3, l3);
                sA[((0 * 2 + kk) * 4 + T) * 32 + l] = make_float4(h0, h1, h2, h3);
                sA[((1 * 2 + kk) * 4 + T) * 32 + l] = make_float4(l0, l1, l2, l3);
            }
            __syncthreads();
            #pragma unroll
            for (int kk = 0; kk < 2; kk++) {
                uint32_t ah[2][4], al[2][4];
                #pragma unroll
                for (int mt = 0; mt < 2; mt++) {
                    int T = wm * 2 + mt;
                    float4 h = sA[((0 * 2 + kk) * 4 + T) * 32 + lane];
                    float4 l = sA[((1 * 2 + kk) * 4 + T) * 32 + lane];
                    ah[mt][0]=__float_as_uint(h.x); ah[mt][1]=__float_as_uint(h.y);
                    ah[mt][2]=__float_as_uint(h.z); ah[mt][3]=__float_as_uint(h.w);
                    al[mt][0]=__float_as_uint(l.x); al[mt][1]=__float_as_uint(l.y);
                    al[mt][2]=__float_as_uint(l.z); al[mt][3]=__float_as_uint(l.w);
                }
                #pragma unroll
                for (int nt = 0; nt < 12; nt++) {
                    int G = wn * 12 + nt;
                    float2 bh = sB[((0 * 2 + kk) * 48 + G) * 32 + lane];
                    float2 bl = sB[((1 * 2 + kk) * 48 + G) * 32 + lane];
                    uint32_t bh0 = __float_as_uint(bh.x), bh1 = __float_as_uint(bh.y);
                    uint32_t bl0 = __float_as_uint(bl.x), bl1 = __float_as_uint(bl.y);
                    #pragma unroll
                    for (int mt = 0; mt < 2; mt++) {
                        mma8(acc1[mt][nt], ah[mt][0], ah[mt][1], ah[mt][2], ah[mt][3], bh0, bh1);
                        mma8(acc1[mt][nt], ah[mt][0], ah[mt][1], ah[mt][2], ah[mt][3], bl0, bl1);
                        mma8(acc1[mt][nt], al[mt][0], al[mt][1], al[mt][2], al[mt][3], bh0, bh1);
                    }
                }
            }
            __syncthreads();
        }

        // write S slab to sPex
        #pragma unroll
        for (int mt = 0; mt < 2; mt++) {
            int row = wm * 32 + mt * 16 + gr;
            #pragma unroll
            for (int nt = 0; nt < 12; nt++) {
                int col = wn * 96 + nt * 8 + 2 * gc;
                sPex[row * PEX_LD + col]           = acc1[mt][nt][0];
                sPex[row * PEX_LD + col + 1]       = acc1[mt][nt][1];
                sPex[(row + 8) * PEX_LD + col]     = acc1[mt][nt][2];
                sPex[(row + 8) * PEX_LD + col + 1] = acc1[mt][nt][3];
            }
        }
        __syncthreads();

        // -------- row softmax (unnormalized exp; rowsum deferred) --------
        #pragma unroll
        for (int rr = 0; rr < DT / 8; rr++) {
            int row = wid * (DT / 8) + rr;
            float v[C_ / 32];
            float mx = -INFINITY;
            #pragma unroll
            for (int u = 0; u < C_ / 32; u++) {
                v[u] = sPex[row * PEX_LD + lane + 32 * u];
                mx = fmaxf(mx, v[u]);
            }
            #pragma unroll
            for (int o = 16; o > 0; o >>= 1)
                mx = fmaxf(mx, __shfl_xor_sync(0xffffffffu, mx, o));
            float ssum = 0.f;
            #pragma unroll
            for (int u = 0; u < C_ / 32; u++) {
                v[u] = __expf(v[u] - mx);
                ssum += v[u];
            }
            #pragma unroll
            for (int o = 16; o > 0; o >>= 1)
                ssum += __shfl_xor_sync(0xffffffffu, ssum, o);
            #pragma unroll
            for (int u = 0; u < C_ / 32; u++)
                sPex[row * PEX_LD + lane + 32 * u] = v[u];
            if (lane == 0) sRinv[row] = 1.0f / ssum;
        }
        __syncthreads();

        // -------- GEMM2: fq_new^T[64][224] = Pexp[64][384] @ Fq^T --------
        float acc2[2][7][4];
        #pragma unroll
        for (int mt = 0; mt < 2; mt++)
            #pragma unroll
            for (int nt = 0; nt < 7; nt++)
                #pragma unroll
                for (int e = 0; e < 4; e++) acc2[mt][nt][e] = 0.f;

        for (int p = 0; p < KP2; p++) {
            const int c0 = p * 16;
            // stage B2: B[k][n] = Fq[t=n][c0+k]
            if (tid < 2 * 4 * 28) {
                int u  = tid;
                int kk = u / 112;
                int rm = u % 112;
                int c  = rm / 28;
                int G  = rm % 28;
                int ck = c0 + kk * 8 + c;
                #pragma unroll
                for (int g = 0; g < 8; g++) {
                    int t = 8 * G + g;
                    float va = (t < T_) ? Fq[t * C_ + ck]     : 0.f;
                    float vb = (t < T_) ? Fq[t * C_ + ck + 4] : 0.f;
                    float ha, la, hb, lb;
                    split_tf32(va, ha, la);
                    split_tf32(vb, hb, lb);
                    sB[((0 * 2 + kk) * 48 + G) * 32 + g * 4 + c] = make_float2(ha, hb);
                    sB[((1 * 2 + kk) * 48 + G) * 32 + g * 4 + c] = make_float2(la, lb);
                }
            }
            // stage A2 (one per thread): A[m][k] = Pexp[m][c0+k]
            {
                int kk = tid >> 7;
                int T  = (tid >> 5) & 3;
                int l  = tid & 31;
                int r  = l >> 2;
                int c  = l & 3;
                int ck = c0 + kk * 8 + c;
                float x0 = sPex[(T * 16 + r) * PEX_LD + ck];
                float x1 = sPex[(T * 16 + r + 8) * PEX_LD + ck];
                float x2 = sPex[(T * 16 + r) * PEX_LD + ck + 4];
                float x3 = sPex[(T * 16 + r + 8) * PEX_LD + ck + 4];
                float h0,l0,h1,l1,h2,l2,h3,l3;
                split_tf32(x0, h0, l0); split_tf32(x1, h1, l1);
                split_tf32(x2, h2, l2); split_tf32(x3, h3, l3);
                sA[((0 * 2 + kk) * 4 + T) * 32 + l] = make_float4(h0, h1, h2, h3);
                sA[((1 * 2 + kk) * 4 + T) * 32 + l] = make_float4(l0, l1, l2, l3);
            }
            __syncthreads();
            #pragma unroll
            for (int kk = 0; kk < 2; kk++) {
                uint32_t ah[2][4], al[2][4];
                #pragma unroll
                for (int mt = 0; mt < 2; mt++) {
                    int T = wm * 2 + mt;
                    float4 h = sA[((0 * 2 + kk) * 4 + T) * 32 + lane];
                    float4 l = sA[((1 * 2 + kk) * 4 + T) * 32 + lane];
                    ah[mt][0]=__float_as_uint(h.x); ah[mt][1]=__float_as_uint(h.y);
                    ah[mt][2]=__float_as_uint(h.z); ah[mt][3]=__float_as_uint(h.w);
                    al[mt][0]=__float_as_uint(l.x); al[mt][1]=__float_as_uint(l.y);
                    al[mt][2]=__float_as_uint(l.z); al[mt][3]=__float_as_uint(l.w);
                }
                #pragma unroll
                for (int nt = 0; nt < 7; nt++) {
                    int G = wn * 7 + nt;
                    float2 bh = sB[((0 * 2 + kk) * 48 + G) * 32 + lane];
                    float2 bl = sB[((1 * 2 + kk) * 48 + G) * 32 + lane];
                    uint32_t bh0 = __float_as_uint(bh.x), bh1 = __float_as_uint(bh.y);
                    uint32_t bl0 = __float_as_uint(bl.x), bl1 = __float_as_uint(bl.y);
                    #pragma unroll
                    for (int mt = 0; mt < 2; mt++) {
                        mma8(acc2[mt][nt], ah[mt][0], ah[mt][1], ah[mt][2], ah[mt][3], bh0, bh1);
                        mma8(acc2[mt][nt], ah[mt][0], ah[mt][1], ah[mt][2], ah[mt][3], bl0, bl1);
                        mma8(acc2[mt][nt], al[mt][0], al[mt][1], al[mt][2], al[mt][3], bh0, bh1);
                    }
                }
            }
            __syncthreads();
        }

        // -------- epilogue: fold 1/rowsum, num/norm2 partials --------
        #pragma unroll
        for (int mt = 0; mt < 2; mt++) {
            int dl1 = wm * 32 + mt * 16 + gr;
            int dl2 = dl1 + 8;
            float rd1 = sRinv[dl1];
            float rd2 = sRinv[dl2];
            int gd1 = d0 + dl1;
            int gd2 = d0 + dl2;
            #pragma unroll
            for (int nt = 0; nt < 7; nt++) {
                int ta = wn * 56 + nt * 8 + 2 * gc;
                int tb = ta + 1;
                float v0 = acc2[mt][nt][0] * rd1;
                float v1 = acc2[mt][nt][1] * rd1;
                float v2 = acc2[mt][nt][2] * rd2;
                float v3 = acc2[mt][nt][3] * rd2;
                float fa1 = 0.f, fa2 = 0.f, fb1 = 0.f, fb2 = 0.f;
                if (ta < T_) { fa1 = Fs[ta * C_ + gd1]; fa2 = Fs[ta * C_ + gd2]; }
                if (tb < T_) { fb1 = Fs[tb * C_ + gd1]; fb2 = Fs[tb * C_ + gd2]; }
                float pn_a = v0 * fa1 + v2 * fa2;
                float pq_a = v0 * v0 + v2 * v2;
                float pn_b = v1 * fb1 + v3 * fb2;
                float pq_b = v1 * v1 + v3 * v3;
                #pragma unroll
                for (int o = 4; o <= 16; o <<= 1) {
                    pn_a += __shfl_xor_sync(0xffffffffu, pn_a, o);
                    pq_a += __shfl_xor_sync(0xffffffffu, pq_a, o);
                    pn_b += __shfl_xor_sync(0xffffffffu, pn_b, o);
                    pq_b += __shfl_xor_sync(0xffffffffu, pq_b, o);
                }
                if (lane < 4) {
                    sPN[wid * NT2 + ta] += pn_a;
                    sPQ[wid * NT2 + ta] += pq_a;
                    sPN[wid * NT2 + tb] += pn_b;
                    sPQ[wid * NT2 + tb] += pq_b;
                }
            }
        }
        __syncthreads();
    }  // slab loop

    // ---- cosine sim per token, max over tokens ----
    float local = -INFINITY;
    for (int t = tid; t < T_; t += TPB) {
        float num = 0.f, nrm = 0.f;
        #pragma unroll
        for (int w = 0; w < 8; w++) {
            num += sPN[w * NT2 + t];
            nrm += sPQ[w * NT2 + t];
        }
        float denom = fmaxf(sqrtf(nrm) * sNfs[t], 1e-8f);
        local = fmaxf(local, num / denom);
    }
    #pragma unroll
    for (int o = 16; o > 0; o >>= 1)
        local = fmaxf(local, __shfl_xor_sync(0xffffffffu, local, o));
    if (lane == 0) sRed[wid] = local;
    __syncthreads();
    if (tid == 0) {
        float m = sRed[0];
        #pragma unroll
        for (int w = 1; w < 8; w++) m = fmaxf(m, sRed[w]);
        g_top1[bx] = m;
    }
}

__global__ void finalize_logits_kernel(float* __restrict__ out) {
    int i = blockIdx.x * blockDim.x + threadIdx.x;
    if (i < B_ * Q_) {
        float s = 0.f;
        #pragma unroll
        for (int n = 0; n < N_; n++) s += g_top1[i * N_ + n];
        out[i] = s * (1.0f / N_);
    }
}

__global__ void cls_kernel(const float* __restrict__ xq,
                           const float* __restrict__ xs,
                           float* __restrict__ out) {
    int w = (blockIdx.x * blockDim.x + threadIdx.x) >> 5;
    int lid = threadIdx.x & 31;
    if (w >= B_ * Q_ * N_) return;
    int nn = w % N_;
    int qq = (w / N_) % Q_;
    int bb = w / (N_ * Q_);
    const float* q = xq + (size_t)(bb * Q_ + qq) * D_;
    const float* s = xs + (size_t)(bb * N_ + nn) * D_;
    float dot = 0.f, nq = 0.f, ns = 0.f;
    #pragma unroll
    for (int u = 0; u < D_ / 32; u++) {
        float a = q[lid + 32 * u];
        float b = s[lid + 32 * u];
        dot += a * b;
        nq += a * a;
        ns += b * b;
    }
    #pragma unroll
    for (int o = 16; o > 0; o >>= 1) {
        dot += __shfl_xor_sync(0xffffffffu, dot, o);
        nq  += __shfl_xor_sync(0xffffffffu, nq, o);
        ns  += __shfl_xor_sync(0xffffffffu, ns, o);
    }
    if (lid == 0) {
        float den = fmaxf(sqrtf(nq), 1e-12f) * fmaxf(sqrtf(ns), 1e-12f);
        out[B_ * Q_ + w] = 10.0f * dot / den;
    }
}

extern "C" void kernel_launch(void* const* d_in, const int* in_sizes, int n_in,
                              void* d_out, int out_size) {
    const float* fq = (const float*)d_in[0];  // (2,75,196,384)
    const float* fs = (const float*)d_in[1];  // (2,5,1,196,384)
    const float* xq = (const float*)d_in[2];  // (2,75,384)
    const float* xs = (const float*)d_in[3];  // (2,5,1,384)
    float* out = (float*)d_out;               // [150 logits][750 cls_logits]

    const size_t smem_bytes = (size_t)SMEM_FLOATS * sizeof(float);
    cudaFuncSetAttribute(episodic_tc_kernel,
                         cudaFuncAttributeMaxDynamicSharedMemorySize,
                         (int)smem_bytes);

    episodic_tc_kernel<<<B_ * Q_ * N_, TPB, smem_bytes>>>(fq, fs);
    finalize_logits_kernel<<<1, 256>>>(out);
    cls_kernel<<<(B_ * Q_ * N_ * 32 + 255) / 256, 256>>>(xq, xs, out);
}

// round 4
// speedup vs baseline: 5.2542x; 5.2529x over previous
#include <cuda_runtime.h>
#include <cuda_bf16.h>
#include <math.h>
#include <stdint.h>

typedef unsigned int u32;

// Problem constants
#define B_ 2
#define Q_ 75
#define N_ 5
#define T_ 196
#define C_ 384
#define D_ 384
#define SCALE (1.0f / 14.0f)

// Tiling
#define TPB 256
#define DT 64
#define NSLAB 6
#define KP1 13           // GEMM1 k16 panels (t: 196->208)
#define KP2 24           // GEMM2 k16 panels (c: 384)
#define NT2 224          // GEMM2 N (t padded)

// packed panel sizes (u32 words)
#define A1_PANEL 1024    // [pl2][T4][lane32] float4
#define B1_PANEL 6144    // [pl2][G48][lane32] float2
#define B2_PANEL 3584    // [pl2][G28][lane32] float2

__device__ u32 g_A1[150 * NSLAB * KP1 * A1_PANEL];  // ~45.7 MB
__device__ u32 g_B1[10 * KP1 * B1_PANEL];           // ~3.2 MB
__device__ u32 g_B2[150 * KP2 * B2_PANEL];          // ~49.2 MB
__device__ float g_top1[B_ * Q_ * N_];

// smem layout (u32 offsets)
#define U_A2   0                        // A2 frags [p24][pl2][T4][reg4][lane32] = 24576
#define U_B    24576                    // B staging dbuf (B1/B2 aliased): 2*6144
#define U_A1   (U_B + 2 * B1_PANEL)     // 36864: A1 dbuf 2*1024
#define U_PN   (U_A1 + 2 * A1_PANEL)    // 38912: [2][224]
#define U_PQ   (U_PN + 2 * NT2)         // 39360
#define U_RINV (U_PQ + 2 * NT2)         // 39808: [64]
#define U_PMAX (U_RINV + 64)            // 39872: [64][4]
#define U_PSUM (U_PMAX + 256)           // 40128
#define U_NFS  (U_PSUM + 256)           // 40384: [224]
#define U_RED  (U_NFS + NT2)            // 40608: [8]
#define U_TOT  (U_RED + 8)              // 40616 u32 = 162464 B

__device__ __forceinline__ u32 bpack_hi(float x0, float x1) {
    __nv_bfloat162 h;
    h.x = __float2bfloat16(x0);
    h.y = __float2bfloat16(x1);
    return *(u32*)&h;
}
__device__ __forceinline__ u32 bpack_lo(float x0, float x1) {
    __nv_bfloat16 h0 = __float2bfloat16(x0);
    __nv_bfloat16 h1 = __float2bfloat16(x1);
    __nv_bfloat162 l;
    l.x = __float2bfloat16(x0 - __bfloat162float(h0));
    l.y = __float2bfloat16(x1 - __bfloat162float(h1));
    return *(u32*)&l;
}
__device__ __forceinline__ void bsplit2(float x0, float x1, u32& hw, u32& lw) {
    __nv_bfloat16 h0 = __float2bfloat16(x0);
    __nv_bfloat16 h1 = __float2bfloat16(x1);
    __nv_bfloat162 hh; hh.x = h0; hh.y = h1;
    hw = *(u32*)&hh;
    __nv_bfloat162 ll;
    ll.x = __float2bfloat16(x0 - __bfloat162float(h0));
    ll.y = __float2bfloat16(x1 - __bfloat162float(h1));
    lw = *(u32*)&ll;
}

__device__ __forceinline__ void mma16(float* c, const u32* a, u32 b0, u32 b1) {
    asm volatile(
        "mma.sync.aligned.m16n8k16.row.col.f32.bf16.bf16.f32 "
        "{%0,%1,%2,%3},{%4,%5,%6,%7},{%8,%9},{%0,%1,%2,%3};"
        : "+f"(c[0]), "+f"(c[1]), "+f"(c[2]), "+f"(c[3])
        : "r"(a[0]), "r"(a[1]), "r"(a[2]), "r"(a[3]), "r"(b0), "r"(b1));
}

__device__ __forceinline__ void cp16(u32 daddr, const void* src) {
    asm volatile("cp.async.cg.shared.global [%0], [%1], 16;" :: "r"(daddr), "l"(src));
}
#define CP_COMMIT() asm volatile("cp.async.commit_group;" ::: "memory")
#define CP_WAIT0()  asm volatile("cp.async.wait_group 0;" ::: "memory")

// ==================== pack kernels ====================

// A1[m=d][k=t] = SCALE * Fq[t][d], fragment dump per (bq, slab, panel)
__global__ void pack_a1(const float* __restrict__ fq) {
    __shared__ float tile[16][65];
    int bid = blockIdx.x;                 // (bq*NSLAB+s)*KP1 + p
    int p  = bid % KP1;
    int s  = (bid / KP1) % NSLAB;
    int bq = bid / (KP1 * NSLAB);
    const float* Fq = fq + (size_t)bq * T_ * C_;
    int d0 = s * DT;
    for (int idx = threadIdx.x; idx < 16 * DT; idx += 256) {
        int k = idx >> 6, d = idx & 63;
        int t = p * 16 + k;
        tile[k][d] = (t < T_) ? SCALE * Fq[(size_t)t * C_ + d0 + d] : 0.f;
    }
    __syncthreads();
    u32* dst = g_A1 + (size_t)bid * A1_PANEL;
    for (int idx = threadIdx.x; idx < A1_PANEL; idx += 256) {
        int pl  = idx >> 9;
        int rem = idx & 511;
        int T   = rem >> 7;
        int lane = (rem >> 2) & 31;
        int reg  = idx & 3;
        int grr = lane >> 2, gcc = lane & 3;
        int dl = T * 16 + grr + ((reg & 1) ? 8 : 0);
        int kl = 2 * gcc + ((reg & 2) ? 8 : 0);
        float x0 = tile[kl][dl], x1 = tile[kl + 1][dl];
        dst[idx] = pl ? bpack_lo(x0, x1) : bpack_hi(x0, x1);
    }
}

// B1[k=t][n=c] = Fs[t][c], fragment dump per (bn, panel)
__global__ void pack_b1(const float* __restrict__ fs) {
    __shared__ float tile[16][385];
    int bid = blockIdx.x;                 // bn*KP1 + p
    int p  = bid % KP1;
    int bn = bid / KP1;
    const float* Fs = fs + (size_t)bn * T_ * C_;
    for (int idx = threadIdx.x; idx < 16 * C_; idx += 256) {
        int k = idx / C_, c = idx % C_;
        int t = p * 16 + k;
        tile[k][c] = (t < T_) ? Fs[(size_t)t * C_ + c] : 0.f;
    }
    __syncthreads();
    u32* dst = g_B1 + (size_t)bid * B1_PANEL;
    for (int idx = threadIdx.x; idx < B1_PANEL; idx += 256) {
        int pl  = idx / 3072;
        int rem = idx % 3072;
        int G   = rem >> 6;
        int lane = (rem >> 1) & 31;
        int reg  = idx & 1;
        int grr = lane >> 2, gcc = lane & 3;
        int n  = G * 8 + grr;
        int kl = 2 * gcc + 8 * reg;
        float x0 = tile[kl][n], x1 = tile[kl + 1][n];
        dst[idx] = pl ? bpack_lo(x0, x1) : bpack_hi(x0, x1);
    }
}

// B2[k=c][n=t] = Fq[t][c], fragment dump per (bq, panel)
__global__ void pack_b2(const float* __restrict__ fq) {
    __shared__ float tile[T_][17];
    int bid = blockIdx.x;                 // bq*KP2 + p
    int p  = bid % KP2;
    int bq = bid / KP2;
    const float* Fq = fq + (size_t)bq * T_ * C_;
    for (int idx = threadIdx.x; idx < T_ * 16; idx += 256) {
        int t = idx >> 4, c = idx & 15;
        tile[t][c] = Fq[(size_t)t * C_ + p * 16 + c];
    }
    __syncthreads();
    u32* dst = g_B2 + (size_t)bid * B2_PANEL;
    for (int idx = threadIdx.x; idx < B2_PANEL; idx += 256) {
        int pl  = idx / 1792;
        int rem = idx % 1792;
        int G   = rem >> 6;
        int lane = (rem >> 1) & 31;
        int reg  = idx & 1;
        int grr = lane >> 2, gcc = lane & 3;
        int t  = G * 8 + grr;
        int kl = 2 * gcc + 8 * reg;
        float x0 = 0.f, x1 = 0.f;
        if (t < T_) { x0 = tile[t][kl]; x1 = tile[t][kl + 1]; }
        dst[idx] = pl ? bpack_lo(x0, x1) : bpack_hi(x0, x1);
    }
}

// ==================== main kernel ====================

__global__ __launch_bounds__(TPB, 1)
void episodic_main(const float* __restrict__ fs_g) {
    extern __shared__ u32 smu[];
    float* smf = (float*)smu;
    const u32 smbase = (u32)__cvta_generic_to_shared(smu);

    const int bx = blockIdx.x;
    const int nn = bx % N_;
    const int bq = bx / N_;          // b*75+q
    const int bb = bq / Q_;
    const int bn = bb * N_ + nn;
    const float* __restrict__ Fs = fs_g + (size_t)bn * T_ * C_;

    const int tid = threadIdx.x;
    const int wid = tid >> 5, lane = tid & 31;
    const int wm = wid >> 2, wn = wid & 3;
    const int gr = lane >> 2, gc = lane & 3;

    // init partials + Fs token norms
    for (int i = tid; i < 2 * NT2; i += TPB) { smf[U_PN + i] = 0.f; smf[U_PQ + i] = 0.f; }
    for (int r = wid; r < T_; r += 8) {
        float s = 0.f;
        #pragma unroll
        for (int u = 0; u < 12; u++) {
            float v = Fs[(size_t)r * C_ + lane + 32 * u];
            s += v * v;
        }
        #pragma unroll
        for (int o = 16; o > 0; o >>= 1) s += __shfl_xor_sync(0xffffffffu, s, o);
        if (lane == 0) smf[U_NFS + r] = sqrtf(s);
    }
    __syncthreads();

    const u32* gB1 = g_B1 + (size_t)bn * KP1 * B1_PANEL;
    const u32* gB2 = g_B2 + (size_t)bq * KP2 * B2_PANEL;

    for (int slab = 0; slab < NSLAB; slab++) {
        const int d0 = slab * DT;
        const u32* gA1 = g_A1 + (size_t)(bq * NSLAB + slab) * KP1 * A1_PANEL;

        // ---------------- GEMM1 ----------------
        float acc1[2][12][4];
        #pragma unroll
        for (int mt = 0; mt < 2; mt++)
            #pragma unroll
            for (int nt = 0; nt < 12; nt++)
                #pragma unroll
                for (int e = 0; e < 4; e++) acc1[mt][nt][e] = 0.f;

        // prefetch panel 0
        {
            const float4* srcB = (const float4*)(gB1);
            u32 dstB = smbase + (U_B) * 4;
            #pragma unroll
            for (int j = 0; j < 6; j++) cp16(dstB + (tid + j * TPB) * 16, srcB + tid + j * TPB);
            const float4* srcA = (const float4*)(gA1);
            cp16(smbase + (U_A1) * 4 + tid * 16, srcA + tid);
            CP_COMMIT();
        }
        for (int p = 0; p < KP1; p++) {
            const int buf = p & 1;
            CP_WAIT0();
            __syncthreads();
            if (p + 1 < KP1) {
                const float4* srcB = (const float4*)(gB1 + (size_t)(p + 1) * B1_PANEL);
                u32 dstB = smbase + (U_B + (buf ^ 1) * B1_PANEL) * 4;
                #pragma unroll
                for (int j = 0; j < 6; j++) cp16(dstB + (tid + j * TPB) * 16, srcB + tid + j * TPB);
                const float4* srcA = (const float4*)(gA1 + (size_t)(p + 1) * A1_PANEL);
                cp16(smbase + (U_A1 + (buf ^ 1) * A1_PANEL) * 4 + tid * 16, srcA + tid);
                CP_COMMIT();
            }
            const u32* bA = smu + U_A1 + buf * A1_PANEL;
            const u32* bB = smu + U_B + buf * B1_PANEL;
            u32 ah[2][4], al[2][4];
            #pragma unroll
            for (int mt = 0; mt < 2; mt++) {
                int T = wm * 2 + mt;
                uint4 h = *(const uint4*)&bA[((0 * 4 + T) * 32 + lane) * 4];
                uint4 l = *(const uint4*)&bA[((1 * 4 + T) * 32 + lane) * 4];
                ah[mt][0] = h.x; ah[mt][1] = h.y; ah[mt][2] = h.z; ah[mt][3] = h.w;
                al[mt][0] = l.x; al[mt][1] = l.y; al[mt][2] = l.z; al[mt][3] = l.w;
            }
            #pragma unroll
            for (int nt = 0; nt < 12; nt++) {
                int G = wn * 12 + nt;
                uint2 bh = *(const uint2*)&bB[((0 * 48 + G) * 32 + lane) * 2];
                uint2 bl = *(const uint2*)&bB[((1 * 48 + G) * 32 + lane) * 2];
                #pragma unroll
                for (int mt = 0; mt < 2; mt++) {
                    mma16(acc1[mt][nt], ah[mt], bh.x, bh.y);
                    mma16(acc1[mt][nt], ah[mt], bl.x, bl.y);
                    mma16(acc1[mt][nt], al[mt], bh.x, bh.y);
                }
            }
        }

        // ---------------- softmax (row max/sum across 4 wn-warps) ----------------
        #pragma unroll
        for (int mt = 0; mt < 2; mt++)
            #pragma unroll
            for (int h = 0; h < 2; h++) {
                float mx = -INFINITY;
                #pragma unroll
                for (int nt = 0; nt < 12; nt++)
                    mx = fmaxf(mx, fmaxf(acc1[mt][nt][2 * h], acc1[mt][nt][2 * h + 1]));
                mx = fmaxf(mx, __shfl_xor_sync(0xffffffffu, mx, 1));
                mx = fmaxf(mx, __shfl_xor_sync(0xffffffffu, mx, 2));
                int row = wm * 32 + mt * 16 + gr + 8 * h;
                if (gc == 0) smf[U_PMAX + row * 4 + wn] = mx;
            }
        __syncthreads();
        #pragma unroll
        for (int mt = 0; mt < 2; mt++)
            #pragma unroll
            for (int h = 0; h < 2; h++) {
                int row = wm * 32 + mt * 16 + gr + 8 * h;
                float gmax = fmaxf(fmaxf(smf[U_PMAX + row * 4], smf[U_PMAX + row * 4 + 1]),
                                   fmaxf(smf[U_PMAX + row * 4 + 2], smf[U_PMAX + row * 4 + 3]));
                float s = 0.f;
                #pragma unroll
                for (int nt = 0; nt < 12; nt++) {
                    float v0 = __expf(acc1[mt][nt][2 * h] - gmax);
                    float v1 = __expf(acc1[mt][nt][2 * h + 1] - gmax);
                    acc1[mt][nt][2 * h] = v0;
                    acc1[mt][nt][2 * h + 1] = v1;
                    s += v0 + v1;
                }
                s += __shfl_xor_sync(0xffffffffu, s, 1);
                s += __shfl_xor_sync(0xffffffffu, s, 2);
                if (gc == 0) smf[U_PSUM + row * 4 + wn] = s;
            }
        __syncthreads();
        #pragma unroll
        for (int mt = 0; mt < 2; mt++)
            #pragma unroll
            for (int h = 0; h < 2; h++) {
                int row = wm * 32 + mt * 16 + gr + 8 * h;
                if (wn == 0 && gc == 0) {
                    float tot = smf[U_PSUM + row * 4] + smf[U_PSUM + row * 4 + 1] +
                                smf[U_PSUM + row * 4 + 2] + smf[U_PSUM + row * 4 + 3];
                    smf[U_RINV + row] = 1.0f / tot;
                }
            }

        // pack Pexp straight into GEMM2 A-fragment layout (reg-major: conflict-free)
        #pragma unroll
        for (int mt = 0; mt < 2; mt++) {
            int T = wm * 2 + mt;
            #pragma unroll
            for (int nt = 0; nt < 12; nt++) {
                int p2 = wn * 6 + (nt >> 1);
                int rb = (nt & 1) * 2;
                u32 hw, lw;
                bsplit2(acc1[mt][nt][0], acc1[mt][nt][1], hw, lw);
                smu[U_A2 + (((p2 * 2 + 0) * 4 + T) * 4 + rb) * 32 + lane] = hw;
                smu[U_A2 + (((p2 * 2 + 1) * 4 + T) * 4 + rb) * 32 + lane] = lw;
                bsplit2(acc1[mt][nt][2], acc1[mt][nt][3], hw, lw);
                smu[U_A2 + (((p2 * 2 + 0) * 4 + T) * 4 + rb + 1) * 32 + lane] = hw;
                smu[U_A2 + (((p2 * 2 + 1) * 4 + T) * 4 + rb + 1) * 32 + lane] = lw;
            }
        }
        __syncthreads();

        // ---------------- GEMM2 ----------------
        float acc2[2][7][4];
        #pragma unroll
        for (int mt = 0; mt < 2; mt++)
            #pragma unroll
            for (int nt = 0; nt < 7; nt++)
                #pragma unroll
                for (int e = 0; e < 4; e++) acc2[mt][nt][e] = 0.f;

        {
            const float4* srcB = (const float4*)(gB2);
            u32 dstB = smbase + (U_B) * 4;
            #pragma unroll
            for (int j = 0; j < 4; j++) {
                int i = tid + j * TPB;
                if (i < 896) cp16(dstB + i * 16, srcB + i);
            }
            CP_COMMIT();
        }
        for (int p = 0; p < KP2; p++) {
            const int buf = p & 1;
            CP_WAIT0();
            __syncthreads();
            if (p + 1 < KP2) {
                const float4* srcB = (const float4*)(gB2 + (size_t)(p + 1) * B2_PANEL);
                u32 dstB = smbase + (U_B + (buf ^ 1) * B1_PANEL) * 4;
                #pragma unroll
                for (int j = 0; j < 4; j++) {
                    int i = tid + j * TPB;
                    if (i < 896) cp16(dstB + i * 16, srcB + i);
                }
                CP_COMMIT();
            }
            const u32* bB = smu + U_B + buf * B1_PANEL;
            u32 ah[2][4], al[2][4];
            #pragma unroll
            for (int mt = 0; mt < 2; mt++) {
                int T = wm * 2 + mt;
                #pragma unroll
                for (int r = 0; r < 4; r++) {
                    ah[mt][r] = smu[U_A2 + (((p * 2 + 0) * 4 + T) * 4 + r) * 32 + lane];
                    al[mt][r] = smu[U_A2 + (((p * 2 + 1) * 4 + T) * 4 + r) * 32 + lane];
                }
            }
            #pragma unroll
            for (int nt = 0; nt < 7; nt++) {
                int G = wn * 7 + nt;
                uint2 bh = *(const uint2*)&bB[((0 * 28 + G) * 32 + lane) * 2];
                uint2 bl = *(const uint2*)&bB[((1 * 28 + G) * 32 + lane) * 2];
                #pragma unroll
                for (int mt = 0; mt < 2; mt++) {
                    mma16(acc2[mt][nt], ah[mt], bh.x, bh.y);
                    mma16(acc2[mt][nt], ah[mt], bl.x, bl.y);
                    mma16(acc2[mt][nt], al[mt], bh.x, bh.y);
                }
            }
        }
        __syncthreads();

        // ---------------- epilogue: rinv, num/norm2 partials ----------------
        #pragma unroll
        for (int nt = 0; nt < 7; nt++) {
            int G = wn * 7 + nt;
            int ta = G * 8 + 2 * gc;
            int tb = ta + 1;
            float pn_a = 0.f, pq_a = 0.f, pn_b = 0.f, pq_b = 0.f;
            #pragma unroll
            for (int mt = 0; mt < 2; mt++) {
                int rb1 = wm * 32 + mt * 16 + gr;
                int rb2 = rb1 + 8;
                float r1 = smf[U_RINV + rb1];
                float r2 = smf[U_RINV + rb2];
                float v0 = acc2[mt][nt][0] * r1;
                float v1 = acc2[mt][nt][1] * r1;
                float v2 = acc2[mt][nt][2] * r2;
                float v3 = acc2[mt][nt][3] * r2;
                int gd1 = d0 + rb1, gd2 = d0 + rb2;
                float fa1 = 0.f, fa2 = 0.f, fb1 = 0.f, fb2 = 0.f;
                if (ta < T_) { fa1 = Fs[(size_t)ta * C_ + gd1]; fa2 = Fs[(size_t)ta * C_ + gd2]; }
                if (tb < T_) { fb1 = Fs[(size_t)tb * C_ + gd1]; fb2 = Fs[(size_t)tb * C_ + gd2]; }
                pn_a += v0 * fa1 + v2 * fa2;
                pq_a += v0 * v0 + v2 * v2;
                pn_b += v1 * fb1 + v3 * fb2;
                pq_b += v1 * v1 + v3 * v3;
            }
            #pragma unroll
            for (int o = 4; o <= 16; o <<= 1) {
                pn_a += __shfl_xor_sync(0xffffffffu, pn_a, o);
                pq_a += __shfl_xor_sync(0xffffffffu, pq_a, o);
                pn_b += __shfl_xor_sync(0xffffffffu, pn_b, o);
                pq_b += __shfl_xor_sync(0xffffffffu, pq_b, o);
            }
            if (lane < 4) {
                smf[U_PN + wm * NT2 + ta] += pn_a;
                smf[U_PQ + wm * NT2 + ta] += pq_a;
                smf[U_PN + wm * NT2 + tb] += pn_b;
                smf[U_PQ + wm * NT2 + tb] += pq_b;
            }
        }
        __syncthreads();
    }  // slab loop

    // cosine sim per token, max over tokens
    float local = -INFINITY;
    if (tid < T_) {
        float num = smf[U_PN + tid] + smf[U_PN + NT2 + tid];
        float nrm = smf[U_PQ + tid] + smf[U_PQ + NT2 + tid];
        float denom = fmaxf(sqrtf(nrm) * smf[U_NFS + tid], 1e-8f);
        local = num / denom;
    }
    #pragma unroll
    for (int o = 16; o > 0; o >>= 1)
        local = fmaxf(local, __shfl_xor_sync(0xffffffffu, local, o));
    if (lane == 0) smf[U_RED + wid] = local;
    __syncthreads();
    if (tid == 0) {
        float m = smf[U_RED];
        #pragma unroll
        for (int w = 1; w < 8; w++) m = fmaxf(m, smf[U_RED + w]);
        g_top1[bx] = m;
    }
}

// ==================== epilogue kernels ====================

__global__ void finalize_logits_kernel(float* __restrict__ out) {
    int i = blockIdx.x * blockDim.x + threadIdx.x;
    if (i < B_ * Q_) {
        float s = 0.f;
        #pragma unroll
        for (int n = 0; n < N_; n++) s += g_top1[i * N_ + n];
        out[i] = s * (1.0f / N_);
    }
}

__global__ void cls_kernel(const float* __restrict__ xq,
                           const float* __restrict__ xs,
                           float* __restrict__ out) {
    int w = (blockIdx.x * blockDim.x + threadIdx.x) >> 5;
    int lid = threadIdx.x & 31;
    if (w >= B_ * Q_ * N_) return;
    int nn = w % N_;
    int qq = (w / N_) % Q_;
    int bb = w / (N_ * Q_);
    const float* q = xq + (size_t)(bb * Q_ + qq) * D_;
    const float* s = xs + (size_t)(bb * N_ + nn) * D_;
    float dot = 0.f, nq = 0.f, ns = 0.f;
    #pragma unroll
    for (int u = 0; u < D_ / 32; u++) {
        float a = q[lid + 32 * u];
        float b = s[lid + 32 * u];
        dot += a * b;
        nq += a * a;
        ns += b * b;
    }
    #pragma unroll
    for (int o = 16; o > 0; o >>= 1) {
        dot += __shfl_xor_sync(0xffffffffu, dot, o);
        nq  += __shfl_xor_sync(0xffffffffu, nq, o);
        ns  += __shfl_xor_sync(0xffffffffu, ns, o);
    }
    if (lid == 0) {
        float den = fmaxf(sqrtf(nq), 1e-12f) * fmaxf(sqrtf(ns), 1e-12f);
        out[B_ * Q_ + w] = 10.0f * dot / den;
    }
}

extern "C" void kernel_launch(void* const* d_in, const int* in_sizes, int n_in,
                              void* d_out, int out_size) {
    const float* fq = (const float*)d_in[0];  // (2,75,196,384)
    const float* fs = (const float*)d_in[1];  // (2,5,1,196,384)
    const float* xq = (const float*)d_in[2];  // (2,75,384)
    const float* xs = (const float*)d_in[3];  // (2,5,1,384)
    float* out = (float*)d_out;               // [150 logits][750 cls_logits]

    pack_a1<<<150 * NSLAB * KP1, 256>>>(fq);
    pack_b1<<<10 * KP1, 256>>>(fs);
    pack_b2<<<150 * KP2, 256>>>(fq);

    const size_t smem_bytes = (size_t)U_TOT * sizeof(u32);
    cudaFuncSetAttribute(episodic_main,
                         cudaFuncAttributeMaxDynamicSharedMemorySize,
                         (int)smem_bytes);
    episodic_main<<<B_ * Q_ * N_, TPB, smem_bytes>>>(fs);

    finalize_logits_kernel<<<1, 256>>>(out);
    cls_kernel<<<(B_ * Q_ * N_ * 32 + 255) / 256, 256>>>(xq, xs, out);
}

// round 6
// speedup vs baseline: 5.5333x; 1.0531x over previous
#include <cuda_runtime.h>
#include <cuda_bf16.h>
#include <math.h>
#include <stdint.h>

typedef unsigned int u32;

// Problem constants
#define B_ 2
#define Q_ 75
#define N_ 5
#define T_ 196
#define C_ 384
#define D_ 384
#define SCALE (1.0f / 14.0f)

// Tiling
#define TPB 256
#define DT 32
#define NSLAB 12
#define KP1 13           // GEMM1 k16 panels (t: 196->208)
#define KP2 24           // GEMM2 k16 panels (c: 384)
#define NT2 224          // GEMM2 N (t padded)

// packed panel sizes (u32 words)
#define A1_PANEL 512     // [pl2][T2][lane32][reg4]
#define B1_PANEL 6144    // [pl2][G48][lane32][reg2]
#define B2_PANEL 3584    // [pl2][G28][lane32][reg2]

__device__ u32 g_A1[150 * NSLAB * KP1 * A1_PANEL];  // ~45.7 MB
__device__ u32 g_B1[10 * KP1 * B1_PANEL];           // ~3.2 MB
__device__ u32 g_B2[150 * KP2 * B2_PANEL];          // ~49.2 MB
__device__ float g_top1[B_ * Q_ * N_];

// smem layout (u32 offsets)
#define U_A2   0                        // A2 frags [p24][pl2][T2][reg4][lane32] = 12288
#define U_B    12288                    // B staging dbuf: 2*6144
#define U_A1   (U_B + 2 * B1_PANEL)     // 24576: A1 dbuf 2*512
#define U_PN   (U_A1 + 2 * A1_PANEL)    // 25600: [2][224]
#define U_PQ   (U_PN + 2 * NT2)         // 26048
#define U_RINV (U_PQ + 2 * NT2)         // 26496: [32]
#define U_PMAX (U_RINV + 32)            // 26528: [32][4]
#define U_PSUM (U_PMAX + 128)           // 26656
#define U_NFS  (U_PSUM + 128)           // 26784: [224]
#define U_RED  (U_NFS + NT2)            // 27008: [8]
#define U_TOT  (U_RED + 8)              // 27016 u32 = 108064 B

__device__ __forceinline__ u32 bpack_hi(float x0, float x1) {
    __nv_bfloat162 h;
    h.x = __float2bfloat16(x0);
    h.y = __float2bfloat16(x1);
    return *(u32*)&h;
}
__device__ __forceinline__ u32 bpack_lo(float x0, float x1) {
    __nv_bfloat16 h0 = __float2bfloat16(x0);
    __nv_bfloat16 h1 = __float2bfloat16(x1);
    __nv_bfloat162 l;
    l.x = __float2bfloat16(x0 - __bfloat162float(h0));
    l.y = __float2bfloat16(x1 - __bfloat162float(h1));
    return *(u32*)&l;
}
__device__ __forceinline__ void bsplit2(float x0, float x1, u32& hw, u32& lw) {
    __nv_bfloat16 h0 = __float2bfloat16(x0);
    __nv_bfloat16 h1 = __float2bfloat16(x1);
    __nv_bfloat162 hh; hh.x = h0; hh.y = h1;
    hw = *(u32*)&hh;
    __nv_bfloat162 ll;
    ll.x = __float2bfloat16(x0 - __bfloat162float(h0));
    ll.y = __float2bfloat16(x1 - __bfloat162float(h1));
    lw = *(u32*)&ll;
}

__device__ __forceinline__ void mma16(float* c, const u32* a, u32 b0, u32 b1) {
    asm volatile(
        "mma.sync.aligned.m16n8k16.row.col.f32.bf16.bf16.f32 "
        "{%0,%1,%2,%3},{%4,%5,%6,%7},{%8,%9},{%0,%1,%2,%3};"
        : "+f"(c[0]), "+f"(c[1]), "+f"(c[2]), "+f"(c[3])
        : "r"(a[0]), "r"(a[1]), "r"(a[2]), "r"(a[3]), "r"(b0), "r"(b1));
}

__device__ __forceinline__ void cp16(u32 daddr, const void* src) {
    asm volatile("cp.async.cg.shared.global [%0], [%1], 16;" :: "r"(daddr), "l"(src));
}
#define CP_COMMIT() asm volatile("cp.async.commit_group;" ::: "memory")
#define CP_WAIT0()  asm volatile("cp.async.wait_group 0;" ::: "memory")

// ==================== pack kernels ====================

// A1[m=d][k=t] = SCALE * Fq[t][d], fragment dump per (bq, slab, panel)
__global__ void pack_a1(const float* __restrict__ fq) {
    __shared__ float tile[16][33];
    int bid = blockIdx.x;                 // (bq*NSLAB+s)*KP1 + p
    int p  = bid % KP1;
    int s  = (bid / KP1) % NSLAB;
    int bq = bid / (KP1 * NSLAB);
    const float* Fq = fq + (size_t)bq * T_ * C_;
    int d0 = s * DT;
    for (int idx = threadIdx.x; idx < 16 * DT; idx += 256) {
        int k = idx >> 5, d = idx & 31;
        int t = p * 16 + k;
        tile[k][d] = (t < T_) ? SCALE * Fq[(size_t)t * C_ + d0 + d] : 0.f;
    }
    __syncthreads();
    u32* dst = g_A1 + (size_t)bid * A1_PANEL;
    for (int idx = threadIdx.x; idx < A1_PANEL; idx += 256) {
        int pl  = idx >> 8;
        int rem = idx & 255;
        int T   = rem >> 7;
        int lane = (rem >> 2) & 31;
        int reg  = idx & 3;
        int grr = lane >> 2, gcc = lane & 3;
        int dl = T * 16 + grr + ((reg & 1) ? 8 : 0);
        int kl = 2 * gcc + ((reg & 2) ? 8 : 0);
        float x0 = tile[kl][dl], x1 = tile[kl + 1][dl];
        dst[idx] = pl ? bpack_lo(x0, x1) : bpack_hi(x0, x1);
    }
}

// B1[k=t][n=c] = Fs[t][c], fragment dump per (bn, panel)
__global__ void pack_b1(const float* __restrict__ fs) {
    __shared__ float tile[16][385];
    int bid = blockIdx.x;                 // bn*KP1 + p
    int p  = bid % KP1;
    int bn = bid / KP1;
    const float* Fs = fs + (size_t)bn * T_ * C_;
    for (int idx = threadIdx.x; idx < 16 * C_; idx += 256) {
        int k = idx / C_, c = idx % C_;
        int t = p * 16 + k;
        tile[k][c] = (t < T_) ? Fs[(size_t)t * C_ + c] : 0.f;
    }
    __syncthreads();
    u32* dst = g_B1 + (size_t)bid * B1_PANEL;
    for (int idx = threadIdx.x; idx < B1_PANEL; idx += 256) {
        int pl  = idx / 3072;
        int rem = idx % 3072;
        int G   = rem >> 6;
        int lane = (rem >> 1) & 31;
        int reg  = idx & 1;
        int grr = lane >> 2, gcc = lane & 3;
        int n  = G * 8 + grr;
        int kl = 2 * gcc + 8 * reg;
        float x0 = tile[kl][n], x1 = tile[kl + 1][n];
        dst[idx] = pl ? bpack_lo(x0, x1) : bpack_hi(x0, x1);
    }
}

// B2[k=c][n=t] = Fq[t][c], fragment dump per (bq, panel)
__global__ void pack_b2(const float* __restrict__ fq) {
    __shared__ float tile[T_][17];
    int bid = blockIdx.x;                 // bq*KP2 + p
    int p  = bid % KP2;
    int bq = bid / KP2;
    const float* Fq = fq + (size_t)bq * T_ * C_;
    for (int idx = threadIdx.x; idx < T_ * 16; idx += 256) {
        int t = idx >> 4, c = idx & 15;
        tile[t][c] = Fq[(size_t)t * C_ + p * 16 + c];
    }
    __syncthreads();
    u32* dst = g_B2 + (size_t)bid * B2_PANEL;
    for (int idx = threadIdx.x; idx < B2_PANEL; idx += 256) {
        int pl  = idx / 1792;
        int rem = idx % 1792;
        int G   = rem >> 6;
        int lane = (rem >> 1) & 31;
        int reg  = idx & 1;
        int grr = lane >> 2, gcc = lane & 3;
        int t  = G * 8 + grr;
        int kl = 2 * gcc + 8 * reg;
        float x0 = 0.f, x1 = 0.f;
        if (t < T_) { x0 = tile[t][kl]; x1 = tile[t][kl + 1]; }
        dst[idx] = pl ? bpack_lo(x0, x1) : bpack_hi(x0, x1);
    }
}

// ==================== main kernel ====================

__global__ __launch_bounds__(TPB, 2)
void episodic_main(const float* __restrict__ fs_g) {
    extern __shared__ u32 smu[];
    float* smf = (float*)smu;
    const u32 smbase = (u32)__cvta_generic_to_shared(smu);

    const int bx = blockIdx.x;
    const int nn = bx % N_;
    const int bq = bx / N_;          // b*75+q
    const int bb = bq / Q_;
    const int bn = bb * N_ + nn;
    const float* __restrict__ Fs = fs_g + (size_t)bn * T_ * C_;

    const int tid = threadIdx.x;
    const int wid = tid >> 5, lane = tid & 31;
    const int wm = wid >> 2, wn = wid & 3;   // wm: m-tile (T index), wn: n/k quarter
    const int gr = lane >> 2, gc = lane & 3;

    // init partials + Fs token norms
    for (int i = tid; i < 2 * NT2; i += TPB) { smf[U_PN + i] = 0.f; smf[U_PQ + i] = 0.f; }
    for (int r = wid; r < T_; r += 8) {
        float s = 0.f;
        #pragma unroll
        for (int u = 0; u < 12; u++) {
            float v = Fs[(size_t)r * C_ + lane + 32 * u];
            s += v * v;
        }
        #pragma unroll
        for (int o = 16; o > 0; o >>= 1) s += __shfl_xor_sync(0xffffffffu, s, o);
        if (lane == 0) smf[U_NFS + r] = sqrtf(s);
    }
    __syncthreads();

    const u32* gB1 = g_B1 + (size_t)bn * KP1 * B1_PANEL;
    const u32* gB2 = g_B2 + (size_t)bq * KP2 * B2_PANEL;

    for (int slab = 0; slab < NSLAB; slab++) {
        const int d0 = slab * DT;
        const u32* gA1 = g_A1 + (size_t)(bq * NSLAB + slab) * KP1 * A1_PANEL;

        // ---------------- GEMM1: S[32][384] ----------------
        float acc1[12][4];
        #pragma unroll
        for (int nt = 0; nt < 12; nt++)
            #pragma unroll
            for (int e = 0; e < 4; e++) acc1[nt][e] = 0.f;

        // prefetch panel 0
        {
            const float4* srcB = (const float4*)(gB1);
            u32 dstB = smbase + (U_B) * 4;
            #pragma unroll
            for (int j = 0; j < 6; j++) cp16(dstB + (tid + j * TPB) * 16, srcB + tid + j * TPB);
            if (tid < 128) {
                const float4* srcA = (const float4*)(gA1);
                cp16(smbase + (U_A1) * 4 + tid * 16, srcA + tid);
            }
            CP_COMMIT();
        }
        for (int p = 0; p < KP1; p++) {
            const int buf = p & 1;
            CP_WAIT0();
            __syncthreads();
            if (p + 1 < KP1) {
                const float4* srcB = (const float4*)(gB1 + (size_t)(p + 1) * B1_PANEL);
                u32 dstB = smbase + (U_B + (buf ^ 1) * B1_PANEL) * 4;
                #pragma unroll
                for (int j = 0; j < 6; j++) cp16(dstB + (tid + j * TPB) * 16, srcB + tid + j * TPB);
                if (tid < 128) {
                    const float4* srcA = (const float4*)(gA1 + (size_t)(p + 1) * A1_PANEL);
                    cp16(smbase + (U_A1 + (buf ^ 1) * A1_PANEL) * 4 + tid * 16, srcA + tid);
                }
                CP_COMMIT();
            }
            const u32* bA = smu + U_A1 + buf * A1_PANEL;
            const u32* bB = smu + U_B + buf * B1_PANEL;
            u32 ah[4], al[4];
            {
                uint4 h = *(const uint4*)&bA[((0 * 2 + wm) * 32 + lane) * 4];
                uint4 l = *(const uint4*)&bA[((1 * 2 + wm) * 32 + lane) * 4];
                ah[0] = h.x; ah[1] = h.y; ah[2] = h.z; ah[3] = h.w;
                al[0] = l.x; al[1] = l.y; al[2] = l.z; al[3] = l.w;
            }
            #pragma unroll
            for (int nt = 0; nt < 12; nt++) {
                int G = wn * 12 + nt;
                uint2 bh = *(const uint2*)&bB[((0 * 48 + G) * 32 + lane) * 2];
                uint2 bl = *(const uint2*)&bB[((1 * 48 + G) * 32 + lane) * 2];
                mma16(acc1[nt], ah, bh.x, bh.y);
                mma16(acc1[nt], ah, bl.x, bl.y);
                mma16(acc1[nt], al, bh.x, bh.y);
            }
        }

        // ---------------- softmax (row max/sum across 4 wn-warps) ----------------
        #pragma unroll
        for (int h = 0; h < 2; h++) {
            float mx = -INFINITY;
            #pragma unroll
            for (int nt = 0; nt < 12; nt++)
                mx = fmaxf(mx, fmaxf(acc1[nt][2 * h], acc1[nt][2 * h + 1]));
            mx = fmaxf(mx, __shfl_xor_sync(0xffffffffu, mx, 1));
            mx = fmaxf(mx, __shfl_xor_sync(0xffffffffu, mx, 2));
            int row = wm * 16 + gr + 8 * h;
            if (gc == 0) smf[U_PMAX + row * 4 + wn] = mx;
        }
        __syncthreads();
        #pragma unroll
        for (int h = 0; h < 2; h++) {
            int row = wm * 16 + gr + 8 * h;
            float gmax = fmaxf(fmaxf(smf[U_PMAX + row * 4], smf[U_PMAX + row * 4 + 1]),
                               fmaxf(smf[U_PMAX + row * 4 + 2], smf[U_PMAX + row * 4 + 3]));
            float s = 0.f;
            #pragma unroll
            for (int nt = 0; nt < 12; nt++) {
                float v0 = __expf(acc1[nt][2 * h] - gmax);
                float v1 = __expf(acc1[nt][2 * h + 1] - gmax);
                acc1[nt][2 * h] = v0;
                acc1[nt][2 * h + 1] = v1;
                s += v0 + v1;
            }
            s += __shfl_xor_sync(0xffffffffu, s, 1);
            s += __shfl_xor_sync(0xffffffffu, s, 2);
            if (gc == 0) smf[U_PSUM + row * 4 + wn] = s;
        }
        __syncthreads();
        if (wn == 0 && gc == 0) {
            #pragma unroll
            for (int h = 0; h < 2; h++) {
                int row = wm * 16 + gr + 8 * h;
                float tot = smf[U_PSUM + row * 4] + smf[U_PSUM + row * 4 + 1] +
                            smf[U_PSUM + row * 4 + 2] + smf[U_PSUM + row * 4 + 3];
                smf[U_RINV + row] = 1.0f / tot;
            }
        }

        // pack Pexp into GEMM2 A-fragment layout (C->A frag match; reg-major, conflict-free)
        #pragma unroll
        for (int nt = 0; nt < 12; nt++) {
            int p2 = wn * 6 + (nt >> 1);
            int rb = (nt & 1) * 2;
            u32 hw, lw;
            bsplit2(acc1[nt][0], acc1[nt][1], hw, lw);
            smu[U_A2 + (((p2 * 2 + 0) * 2 + wm) * 4 + rb) * 32 + lane] = hw;
            smu[U_A2 + (((p2 * 2 + 1) * 2 + wm) * 4 + rb) * 32 + lane] = lw;
            bsplit2(acc1[nt][2], acc1[nt][3], hw, lw);
            smu[U_A2 + (((p2 * 2 + 0) * 2 + wm) * 4 + rb + 1) * 32 + lane] = hw;
            smu[U_A2 + (((p2 * 2 + 1) * 2 + wm) * 4 + rb + 1) * 32 + lane] = lw;
        }
        __syncthreads();

        // ---------------- GEMM2: fq_new^T[32][224] ----------------
        float acc2[7][4];
        #pragma unroll
        for (int nt = 0; nt < 7; nt++)
            #pragma unroll
            for (int e = 0; e < 4; e++) acc2[nt][e] = 0.f;

        {
            const float4* srcB = (const float4*)(gB2);
            u32 dstB = smbase + (U_B) * 4;
            #pragma unroll
            for (int j = 0; j < 4; j++) {
                int i = tid + j * TPB;
                if (i < 896) cp16(dstB + i * 16, srcB + i);
            }
            CP_COMMIT();
        }
        for (int p = 0; p < KP2; p++) {
            const int buf = p & 1;
            CP_WAIT0();
            __syncthreads();
            if (p + 1 < KP2) {
                const float4* srcB = (const float4*)(gB2 + (size_t)(p + 1) * B2_PANEL);
                u32 dstB = smbase + (U_B + (buf ^ 1) * B1_PANEL) * 4;
                #pragma unroll
                for (int j = 0; j < 4; j++) {
                    int i = tid + j * TPB;
                    if (i < 896) cp16(dstB + i * 16, srcB + i);
                }
                CP_COMMIT();
            }
            const u32* bB = smu + U_B + buf * B1_PANEL;
            u32 ah[4], al[4];
            #pragma unroll
            for (int r = 0; r < 4; r++) {
                ah[r] = smu[U_A2 + (((p * 2 + 0) * 2 + wm) * 4 + r) * 32 + lane];
                al[r] = smu[U_A2 + (((p * 2 + 1) * 2 + wm) * 4 + r) * 32 + lane];
            }
            #pragma unroll
            for (int nt = 0; nt < 7; nt++) {
                int G = wn * 7 + nt;
                uint2 bh = *(const uint2*)&bB[((0 * 28 + G) * 32 + lane) * 2];
                uint2 bl = *(const uint2*)&bB[((1 * 28 + G) * 32 + lane) * 2];
                mma16(acc2[nt], ah, bh.x, bh.y);
                mma16(acc2[nt], ah, bl.x, bl.y);
                mma16(acc2[nt], al, bh.x, bh.y);
            }
        }
        __syncthreads();

        // ---------------- epilogue: rinv, num/norm2 partials ----------------
        {
            int rb1 = wm * 16 + gr;
            int rb2 = rb1 + 8;
            float r1 = smf[U_RINV + rb1];
            float r2 = smf[U_RINV + rb2];
            int gd1 = d0 + rb1, gd2 = d0 + rb2;
            #pragma unroll
            for (int nt = 0; nt < 7; nt++) {
                int G = wn * 7 + nt;
                int ta = G * 8 + 2 * gc;
                int tb = ta + 1;
                float v0 = acc2[nt][0] * r1;
                float v1 = acc2[nt][1] * r1;
                float v2 = acc2[nt][2] * r2;
                float v3 = acc2[nt][3] * r2;
                float fa1 = 0.f, fa2 = 0.f, fb1 = 0.f, fb2 = 0.f;
                if (ta < T_) { fa1 = Fs[(size_t)ta * C_ + gd1]; fa2 = Fs[(size_t)ta * C_ + gd2]; }
                if (tb < T_) { fb1 = Fs[(size_t)tb * C_ + gd1]; fb2 = Fs[(size_t)tb * C_ + gd2]; }
                float pn_a = v0 * fa1 + v2 * fa2;
                float pq_a = v0 * v0 + v2 * v2;
                float pn_b = v1 * fb1 + v3 * fb2;
                float pq_b = v1 * v1 + v3 * v3;
                #pragma unroll
                for (int o = 4; o <= 16; o <<= 1) {
                    pn_a += __shfl_xor_sync(0xffffffffu, pn_a, o);
                    pq_a += __shfl_xor_sync(0xffffffffu, pq_a, o);
                    pn_b += __shfl_xor_sync(0xffffffffu, pn_b, o);
                    pq_b += __shfl_xor_sync(0xffffffffu, pq_b, o);
                }
                if (lane < 4) {
                    smf[U_PN + wm * NT2 + ta] += pn_a;
                    smf[U_PQ + wm * NT2 + ta] += pq_a;
                    smf[U_PN + wm * NT2 + tb] += pn_b;
                    smf[U_PQ + wm * NT2 + tb] += pq_b;
                }
            }
        }
        __syncthreads();
    }  // slab loop

    // cosine sim per token, max over tokens
    float local = -INFINITY;
    if (tid < T_) {
        float num = smf[U_PN + tid] + smf[U_PN + NT2 + tid];
        float nrm = smf[U_PQ + tid] + smf[U_PQ + NT2 + tid];
        float denom = fmaxf(sqrtf(nrm) * smf[U_NFS + tid], 1e-8f);
        local = num / denom;
    }
    #pragma unroll
    for (int o = 16; o > 0; o >>= 1)
        local = fmaxf(local, __shfl_xor_sync(0xffffffffu, local, o));
    if (lane == 0) smf[U_RED + wid] = local;
    __syncthreads();
    if (tid == 0) {
        float m = smf[U_RED];
        #pragma unroll
        for (int w = 1; w < 8; w++) m = fmaxf(m, smf[U_RED + w]);
        g_top1[bx] = m;
    }
}

// ==================== epilogue kernels ====================

__global__ void finalize_logits_kernel(float* __restrict__ out) {
    int i = blockIdx.x * blockDim.x + threadIdx.x;
    if (i < B_ * Q_) {
        float s = 0.f;
        #pragma unroll
        for (int n = 0; n < N_; n++) s += g_top1[i * N_ + n];
        out[i] = s * (1.0f / N_);
    }
}

__global__ void cls_kernel(const float* __restrict__ xq,
                           const float* __restrict__ xs,
                           float* __restrict__ out) {
    int w = (blockIdx.x * blockDim.x + threadIdx.x) >> 5;
    int lid = threadIdx.x & 31;
    if (w >= B_ * Q_ * N_) return;
    int nn = w % N_;
    int qq = (w / N_) % Q_;
    int bb = w / (N_ * Q_);
    const float* q = xq + (size_t)(bb * Q_ + qq) * D_;
    const float* s = xs + (size_t)(bb * N_ + nn) * D_;
    float dot = 0.f, nq = 0.f, ns = 0.f;
    #pragma unroll
    for (int u = 0; u < D_ / 32; u++) {
        float a = q[lid + 32 * u];
        float b = s[lid + 32 * u];
        dot += a * b;
        nq += a * a;
        ns += b * b;
    }
    #pragma unroll
    for (int o = 16; o > 0; o >>= 1) {
        dot += __shfl_xor_sync(0xffffffffu, dot, o);
        nq  += __shfl_xor_sync(0xffffffffu, nq, o);
        ns  += __shfl_xor_sync(0xffffffffu, ns, o);
    }
    if (lid == 0) {
        float den = fmaxf(sqrtf(nq), 1e-12f) * fmaxf(sqrtf(ns), 1e-12f);
        out[B_ * Q_ + w] = 10.0f * dot / den;
    }
}

extern "C" void kernel_launch(void* const* d_in, const int* in_sizes, int n_in,
                              void* d_out, int out_size) {
    const float* fq = (const float*)d_in[0];  // (2,75,196,384)
    const float* fs = (const float*)d_in[1];  // (2,5,1,196,384)
    const float* xq = (const float*)d_in[2];  // (2,75,384)
    const float* xs = (const float*)d_in[3];  // (2,5,1,384)
    float* out = (float*)d_out;               // [150 logits][750 cls_logits]

    pack_a1<<<150 * NSLAB * KP1, 256>>>(fq);
    pack_b1<<<10 * KP1, 256>>>(fs);
    pack_b2<<<150 * KP2, 256>>>(fq);

    const size_t smem_bytes = (size_t)U_TOT * sizeof(u32);
    cudaFuncSetAttribute(episodic_main,
                         cudaFuncAttributeMaxDynamicSharedMemorySize,
                         (int)smem_bytes);
    episodic_main<<<B_ * Q_ * N_, TPB, smem_bytes>>>(fs);

    finalize_logits_kernel<<<1, 256>>>(out);
    cls_kernel<<<(B_ * Q_ * N_ * 32 + 255) / 256, 256>>>(xq, xs, out);
}